// round 2
// baseline (speedup 1.0000x reference)
#include <cuda_runtime.h>
#include <math.h>

// ---------------- static problem shape ----------------
#define Bb 16
#define Ss 512
#define Nn 16
#define WD 300
#define ED 64
#define SD 512
#define NK1 364           // WD+ED
#define NK2 576           // SD+ED
#define Mrows (Bb*Ss)     // 8192
#define NLAYERS 3

// ---------------- scratch (device globals; no allocations) ----------------
__device__ float g_in_rep [(size_t)Mrows*NK1];
__device__ float g_out_rep[(size_t)Mrows*NK1];
__device__ float g_w_terms[(size_t)4*Mrows*SD];
__device__ float g_hin    [(size_t)Mrows*NK2];
__device__ float g_hout   [(size_t)Mrows*NK2];
__device__ float g_gates  [(size_t)4*Mrows*SD];
__device__ float g_cell   [(size_t)Mrows*SD];

// ---------------- kernel 1: static neighbor word+edge sums ----------------
__global__ void prep_rep_kernel(const float* __restrict__ word,
                                const float* __restrict__ edge_emb,
                                const int* __restrict__ in_idx,
                                const int* __restrict__ in_edges,
                                const float* __restrict__ in_mask,
                                const int* __restrict__ out_idx,
                                const int* __restrict__ out_edges,
                                const float* __restrict__ out_mask)
{
    int node = blockIdx.x;
    int b = node / Ss;
    __shared__ int   s_idx [2][Nn];
    __shared__ int   s_edge[2][Nn];
    __shared__ float s_msk [2][Nn];
    int tid = threadIdx.x;
    if (tid < Nn) {
        s_idx [0][tid] = in_idx  [(size_t)node*Nn + tid];
        s_edge[0][tid] = in_edges[(size_t)node*Nn + tid];
        s_msk [0][tid] = in_mask [(size_t)node*Nn + tid];
        s_idx [1][tid] = out_idx  [(size_t)node*Nn + tid];
        s_edge[1][tid] = out_edges[(size_t)node*Nn + tid];
        s_msk [1][tid] = out_mask [(size_t)node*Nn + tid];
    }
    __syncthreads();

    #pragma unroll
    for (int dir = 0; dir < 2; dir++) {
        float* rep = dir ? g_out_rep : g_in_rep;
        for (int d = tid; d < WD; d += blockDim.x) {
            float acc = 0.f;
            #pragma unroll
            for (int n = 0; n < Nn; n++)
                acc += s_msk[dir][n] * word[((size_t)b*Ss + s_idx[dir][n])*WD + d];
            rep[(size_t)node*NK1 + d] = acc;
        }
        for (int d = tid; d < ED; d += blockDim.x) {
            float acc = 0.f;
            #pragma unroll
            for (int n = 0; n < Nn; n++)
                acc += s_msk[dir][n] * edge_emb[(size_t)s_edge[dir][n]*ED + d];
            rep[(size_t)node*NK1 + WD + d] = acc;
        }
    }
}

// ---------------- kernel 2: per-layer hidden gather ----------------
__global__ void gather_h_kernel(const float* __restrict__ H,
                                const float* __restrict__ seq_mask,
                                const int* __restrict__ in_idx,
                                const float* __restrict__ in_mask,
                                const int* __restrict__ out_idx,
                                const float* __restrict__ out_mask)
{
    int node = blockIdx.x;
    int b = node / Ss;
    float sm = seq_mask[node];
    __shared__ int   s_idx[2][Nn];
    __shared__ float s_msk[2][Nn];
    int tid = threadIdx.x;
    if (tid < Nn) {
        s_idx[0][tid] = in_idx [(size_t)node*Nn + tid];
        s_msk[0][tid] = in_mask[(size_t)node*Nn + tid];
        s_idx[1][tid] = out_idx [(size_t)node*Nn + tid];
        s_msk[1][tid] = out_mask[(size_t)node*Nn + tid];
    }
    __syncthreads();

    const float* Hb = H + (size_t)b*Ss*SD;
    for (int d = tid; d < SD; d += blockDim.x) {
        float ai = 0.f, ao = 0.f;
        #pragma unroll
        for (int n = 0; n < Nn; n++) {
            ai += s_msk[0][n] * Hb[(size_t)s_idx[0][n]*SD + d];
            ao += s_msk[1][n] * Hb[(size_t)s_idx[1][n]*SD + d];
        }
        g_hin [(size_t)node*NK2 + d] = ai * sm;
        g_hout[(size_t)node*NK2 + d] = ao * sm;
    }
    for (int j = tid; j < ED; j += blockDim.x) {
        g_hin [(size_t)node*NK2 + SD + j] = sm * g_in_rep [(size_t)node*NK1 + WD + j];
        g_hout[(size_t)node*NK2 + SD + j] = sm * g_out_rep[(size_t)node*NK1 + WD + j];
    }
}

// ---------------- kernel 3: dual-A 4-gate SGEMM ----------------
// C[g, row, col] = A1[row,:]*W1[g,:,col] + A2[row,:]*W2[g,:,col] (+bias | +addC)
#define BM 128
#define BN 64
#define BK 8
__global__ __launch_bounds__(256)
void gemm_kernel(const float* __restrict__ A1, const float* __restrict__ W1,
                 const float* __restrict__ A2, const float* __restrict__ W2,
                 const float* __restrict__ bias, const float* __restrict__ addC,
                 float* __restrict__ C, int K)
{
    __shared__ __align__(16) float sA[BK][BM];
    __shared__ __align__(16) float sB[BK][BN];

    int g    = blockIdx.z;
    int row0 = blockIdx.x * BM;
    int col0 = blockIdx.y * BN;
    int tid  = threadIdx.x;
    int tx = tid & 15;          // 16 columns of 4
    int ty = tid >> 4;          // 16 rows of 8

    float acc[8][4];
    #pragma unroll
    for (int i = 0; i < 8; i++)
        #pragma unroll
        for (int j = 0; j < 4; j++) acc[i][j] = 0.f;

    #pragma unroll
    for (int dir = 0; dir < 2; dir++) {
        const float* A = dir ? A2 : A1;
        const float* W = (dir ? W2 : W1) + (size_t)g * K * SD;
        for (int k0 = 0; k0 < K; k0 += BK) {
            #pragma unroll
            for (int it = 0; it < 4; it++) {
                int idx = tid + it * 256;
                int m = idx >> 3, kk = idx & 7;
                int kg = k0 + kk;
                sA[kk][m] = (kg < K) ? A[(size_t)(row0 + m)*K + kg] : 0.f;
            }
            #pragma unroll
            for (int it = 0; it < 2; it++) {
                int idx = tid + it * 256;
                int kk = idx >> 6, n = idx & 63;
                int kg = k0 + kk;
                sB[kk][n] = (kg < K) ? W[(size_t)kg*SD + col0 + n] : 0.f;
            }
            __syncthreads();
            #pragma unroll
            for (int kk = 0; kk < BK; kk++) {
                float4 b0 = reinterpret_cast<const float4*>(&sB[kk][0])[tx];
                float4 a0 = reinterpret_cast<const float4*>(&sA[kk][0])[ty*2];
                float4 a1 = reinterpret_cast<const float4*>(&sA[kk][0])[ty*2 + 1];
                float av[8] = {a0.x,a0.y,a0.z,a0.w,a1.x,a1.y,a1.z,a1.w};
                float bv[4] = {b0.x,b0.y,b0.z,b0.w};
                #pragma unroll
                for (int i = 0; i < 8; i++)
                    #pragma unroll
                    for (int j = 0; j < 4; j++)
                        acc[i][j] += av[i] * bv[j];
            }
            __syncthreads();
        }
    }

    #pragma unroll
    for (int i = 0; i < 8; i++) {
        int row = row0 + ty*8 + i;
        size_t base = ((size_t)g*Mrows + row)*SD;
        #pragma unroll
        for (int j = 0; j < 4; j++) {
            int col = col0 + tx*4 + j;
            float v = acc[i][j];
            if (bias) v += bias[g*SD + col];
            if (addC) v += addC[base + col];
            C[base + col] = v;
        }
    }
}

// ---------------- kernel 4: LSTM elementwise update ----------------
__global__ void lstm_kernel(const float* __restrict__ seq_mask,
                            float* __restrict__ rep_out,
                            float* __restrict__ finalH,
                            float* __restrict__ finalC,
                            int first)
{
    size_t i = (size_t)blockIdx.x * blockDim.x + threadIdx.x;
    const size_t GS = (size_t)Mrows * SD;
    if (i >= GS) return;
    int row = (int)(i / SD);
    float sm = seq_mask[row];

    float g0 = g_gates[i];
    float g1 = g_gates[GS + i];
    float g2 = g_gates[2*GS + i];
    float g3 = g_gates[3*GS + i];

    float ig = 1.f / (1.f + expf(-g0));
    float fg = 1.f / (1.f + expf(-g1));
    float og = 1.f / (1.f + expf(-g2));
    float ci = tanhf(g3);

    float cp = first ? 0.f : g_cell[i];
    float tc = fg * cp + ig * ci;
    float th = og * tanhf(tc);
    float c = tc * sm, h = th * sm;

    g_cell[i]  = c;
    rep_out[i] = h;
    if (finalH) { finalH[i] = h; finalC[i] = c; }
}

// ---------------- launch ----------------
extern "C" void kernel_launch(void* const* d_in, const int* in_sizes, int n_in,
                              void* d_out, int out_size)
{
    const float* word     = (const float*)d_in[0];
    const float* sent     = (const float*)d_in[1];
    const float* seq_mask = (const float*)d_in[2];
    const float* in_mask  = (const float*)d_in[3];
    const float* out_mask = (const float*)d_in[4];
    const float* edge_emb = (const float*)d_in[5];
    const float* Wg_in    = (const float*)d_in[6];
    const float* Ug_in    = (const float*)d_in[7];
    const float* Wg_out   = (const float*)d_in[8];
    const float* Ug_out   = (const float*)d_in[9];
    const float* bvec     = (const float*)d_in[10];
    const int*   in_idx   = (const int*)d_in[11];
    const int*   in_edges = (const int*)d_in[12];
    const int*   out_idx  = (const int*)d_in[13];
    const int*   out_edges= (const int*)d_in[14];
    float* out = (float*)d_out;

    // device addresses of scratch globals (host-side query; capture-safe)
    float *p_in_rep, *p_out_rep, *p_w_terms, *p_hin, *p_hout, *p_gates;
    cudaGetSymbolAddress((void**)&p_in_rep,  g_in_rep);
    cudaGetSymbolAddress((void**)&p_out_rep, g_out_rep);
    cudaGetSymbolAddress((void**)&p_w_terms, g_w_terms);
    cudaGetSymbolAddress((void**)&p_hin,     g_hin);
    cudaGetSymbolAddress((void**)&p_hout,    g_hout);
    cudaGetSymbolAddress((void**)&p_gates,   g_gates);

    const size_t GS = (size_t)Mrows * SD;

    // 1) static neighbor sums
    prep_rep_kernel<<<Mrows, 128>>>(word, edge_emb, in_idx, in_edges, in_mask,
                                    out_idx, out_edges, out_mask);

    // 2) w_terms = in_rep@Wg_in + out_rep@Wg_out + b
    {
        dim3 grid(Mrows/BM, SD/BN, 4);
        gemm_kernel<<<grid, 256>>>(p_in_rep, Wg_in, p_out_rep, Wg_out,
                                   bvec, nullptr, p_w_terms, NK1);
    }

    // 3) layers
    for (int l = 0; l < NLAYERS; l++) {
        const float* H = (l == 0) ? sent : (out + (size_t)(l-1)*GS);
        gather_h_kernel<<<Mrows, 256>>>(H, seq_mask, in_idx, in_mask, out_idx, out_mask);

        dim3 grid(Mrows/BM, SD/BN, 4);
        gemm_kernel<<<grid, 256>>>(p_hin, Ug_in, p_hout, Ug_out,
                                   nullptr, p_w_terms, p_gates, NK2);

        float* repL   = out + (size_t)l*GS;
        float* finalH = (l == NLAYERS-1) ? (out + 3*GS) : nullptr;
        float* finalC = (l == NLAYERS-1) ? (out + 4*GS) : nullptr;
        lstm_kernel<<<(unsigned)((GS + 255)/256), 256>>>(seq_mask, repL, finalH, finalC,
                                                         (l == 0) ? 1 : 0);
    }
}

// round 4
// speedup vs baseline: 2.9559x; 2.9559x over previous
#include <cuda_runtime.h>
#include <cuda_bf16.h>
#include <math.h>
#include <stdint.h>

// ---------------- static problem shape ----------------
#define Bb 16
#define Ss 512
#define Nn 16
#define WD 300
#define ED 64
#define SD 512
#define NK1 364           // WD+ED
#define KP1 384           // padded to 32
#define NK2 576           // SD+ED
#define KP2 576
#define Mrows (Bb*Ss)     // 8192
#define NT 2048           // 4 gates * SD, interleaved n = c*4+g
#define NLAYERS 3

// ---------------- scratch (device globals; no allocations) ----------------
__device__ __align__(256) __nv_bfloat16 g_irep_hi[(size_t)Mrows*KP1];
__device__ __align__(256) __nv_bfloat16 g_irep_lo[(size_t)Mrows*KP1];
__device__ __align__(256) __nv_bfloat16 g_orep_hi[(size_t)Mrows*KP1];
__device__ __align__(256) __nv_bfloat16 g_orep_lo[(size_t)Mrows*KP1];
__device__ __align__(256) float         g_iedge  [(size_t)Mrows*ED];
__device__ __align__(256) float         g_oedge  [(size_t)Mrows*ED];
__device__ __align__(256) __nv_bfloat16 g_hin_hi [(size_t)Mrows*KP2];
__device__ __align__(256) __nv_bfloat16 g_hin_lo [(size_t)Mrows*KP2];
__device__ __align__(256) __nv_bfloat16 g_hout_hi[(size_t)Mrows*KP2];
__device__ __align__(256) __nv_bfloat16 g_hout_lo[(size_t)Mrows*KP2];
__device__ __align__(256) __nv_bfloat16 g_Win_hi [(size_t)NT*KP1];
__device__ __align__(256) __nv_bfloat16 g_Win_lo [(size_t)NT*KP1];
__device__ __align__(256) __nv_bfloat16 g_Wout_hi[(size_t)NT*KP1];
__device__ __align__(256) __nv_bfloat16 g_Wout_lo[(size_t)NT*KP1];
__device__ __align__(256) __nv_bfloat16 g_Uin_hi [(size_t)NT*KP2];
__device__ __align__(256) __nv_bfloat16 g_Uin_lo [(size_t)NT*KP2];
__device__ __align__(256) __nv_bfloat16 g_Uout_hi[(size_t)NT*KP2];
__device__ __align__(256) __nv_bfloat16 g_Uout_lo[(size_t)NT*KP2];
__device__ __align__(256) float         g_bias_i [NT];
__device__ __align__(256) float         g_wterms [(size_t)Mrows*NT];
__device__ __align__(256) float         g_cell   [(size_t)Mrows*SD];

// ---------------- helpers ----------------
__device__ __forceinline__ uint32_t smem_u32(const void* p) {
    uint32_t a;
    asm("{ .reg .u64 t; cvta.to.shared.u64 t, %1; cvt.u32.u64 %0, t; }" : "=r"(a) : "l"(p));
    return a;
}
__device__ __forceinline__ void cpasync16(uint32_t dst, const void* src) {
    asm volatile("cp.async.ca.shared.global [%0], [%1], 16;" :: "r"(dst), "l"(src));
}
#define CP_COMMIT() asm volatile("cp.async.commit_group;" ::: "memory")
#define CP_WAIT(n)  asm volatile("cp.async.wait_group %0;" :: "n"(n) : "memory")

__device__ __forceinline__ void ldm_x4(uint32_t* r, uint32_t addr) {
    asm volatile("ldmatrix.sync.aligned.m8n8.x4.shared.b16 {%0,%1,%2,%3}, [%4];"
        : "=r"(r[0]), "=r"(r[1]), "=r"(r[2]), "=r"(r[3]) : "r"(addr));
}
__device__ __forceinline__ void mma16816(float* d, const uint32_t* a, uint32_t b0, uint32_t b1) {
    asm volatile("mma.sync.aligned.m16n8k16.row.col.f32.bf16.bf16.f32 "
        "{%0,%1,%2,%3}, {%4,%5,%6,%7}, {%8,%9}, {%0,%1,%2,%3};"
        : "+f"(d[0]), "+f"(d[1]), "+f"(d[2]), "+f"(d[3])
        : "r"(a[0]), "r"(a[1]), "r"(a[2]), "r"(a[3]), "r"(b0), "r"(b1));
}
__device__ __forceinline__ void split2(float v, __nv_bfloat16& hi, __nv_bfloat16& lo) {
    hi = __float2bfloat16(v);
    lo = __float2bfloat16(v - __bfloat162float(hi));
}
__device__ __forceinline__ float sigf(float x) { return 1.f / (1.f + __expf(-x)); }

// ---------------- weight transpose + split: W[g][k][c] -> Bt[(c*4+g)][k] ----------------
template<int KSRC, int KPAD>
__global__ void conv_w_kernel(const float* __restrict__ W,
                              __nv_bfloat16* __restrict__ dhi,
                              __nv_bfloat16* __restrict__ dlo)
{
    __shared__ float t[32][33];
    int g = blockIdx.z, k0 = blockIdx.x * 32, c0 = blockIdx.y * 32;
    int tx = threadIdx.x, ty = threadIdx.y;   // 32 x 8
    #pragma unroll
    for (int i = 0; i < 4; i++) {
        int k = k0 + ty + i * 8;
        float v = (k < KSRC) ? W[((size_t)g * KSRC + k) * SD + c0 + tx] : 0.f;
        t[ty + i * 8][tx] = v;
    }
    __syncthreads();
    #pragma unroll
    for (int i = 0; i < 4; i++) {
        int c = ty + i * 8;
        int n = (c0 + c) * 4 + g;
        float v = t[tx][c];
        __nv_bfloat16 hi, lo; split2(v, hi, lo);
        dhi[(size_t)n * KPAD + k0 + tx] = hi;
        dlo[(size_t)n * KPAD + k0 + tx] = lo;
    }
}

__global__ void bias_kernel(const float* __restrict__ b) {
    int n = blockIdx.x * 256 + threadIdx.x;
    if (n < NT) g_bias_i[n] = b[(n & 3) * SD + (n >> 2)];
}

// ---------------- static neighbor word+edge sums (split bf16 out) ----------------
__global__ void prep_rep_kernel(const float* __restrict__ word,
                                const float* __restrict__ edge_emb,
                                const int* __restrict__ in_idx,
                                const int* __restrict__ in_edges,
                                const float* __restrict__ in_mask,
                                const int* __restrict__ out_idx,
                                const int* __restrict__ out_edges,
                                const float* __restrict__ out_mask)
{
    int node = blockIdx.x;
    int b = node / Ss;
    __shared__ int   s_idx [2][Nn];
    __shared__ int   s_edge[2][Nn];
    __shared__ float s_msk [2][Nn];
    int tid = threadIdx.x;
    if (tid < Nn) {
        s_idx [0][tid] = in_idx  [(size_t)node*Nn + tid];
        s_edge[0][tid] = in_edges[(size_t)node*Nn + tid];
        s_msk [0][tid] = in_mask [(size_t)node*Nn + tid];
        s_idx [1][tid] = out_idx  [(size_t)node*Nn + tid];
        s_edge[1][tid] = out_edges[(size_t)node*Nn + tid];
        s_msk [1][tid] = out_mask [(size_t)node*Nn + tid];
    }
    __syncthreads();

    #pragma unroll
    for (int dir = 0; dir < 2; dir++) {
        __nv_bfloat16* rh = dir ? g_orep_hi : g_irep_hi;
        __nv_bfloat16* rl = dir ? g_orep_lo : g_irep_lo;
        float* ed = dir ? g_oedge : g_iedge;
        for (int d = tid; d < WD; d += blockDim.x) {
            float acc = 0.f;
            #pragma unroll
            for (int n = 0; n < Nn; n++)
                acc += s_msk[dir][n] * word[((size_t)b*Ss + s_idx[dir][n])*WD + d];
            __nv_bfloat16 hi, lo; split2(acc, hi, lo);
            rh[(size_t)node*KP1 + d] = hi;
            rl[(size_t)node*KP1 + d] = lo;
        }
        for (int d = tid; d < ED; d += blockDim.x) {
            float acc = 0.f;
            #pragma unroll
            for (int n = 0; n < Nn; n++)
                acc += s_msk[dir][n] * edge_emb[(size_t)s_edge[dir][n]*ED + d];
            ed[(size_t)node*ED + d] = acc;
            __nv_bfloat16 hi, lo; split2(acc, hi, lo);
            rh[(size_t)node*KP1 + WD + d] = hi;
            rl[(size_t)node*KP1 + WD + d] = lo;
        }
        for (int d = NK1 + tid; d < KP1; d += blockDim.x) {
            rh[(size_t)node*KP1 + d] = __float2bfloat16(0.f);
            rl[(size_t)node*KP1 + d] = __float2bfloat16(0.f);
        }
    }
}

// ---------------- per-layer hidden gather (split bf16 out) ----------------
__global__ void gather_h_kernel(const float* __restrict__ H,
                                const float* __restrict__ seq_mask,
                                const int* __restrict__ in_idx,
                                const float* __restrict__ in_mask,
                                const int* __restrict__ out_idx,
                                const float* __restrict__ out_mask)
{
    int node = blockIdx.x;
    int b = node / Ss;
    float sm = seq_mask[node];
    __shared__ int   s_idx[2][Nn];
    __shared__ float s_msk[2][Nn];
    int tid = threadIdx.x;
    if (tid < Nn) {
        s_idx[0][tid] = in_idx [(size_t)node*Nn + tid];
        s_msk[0][tid] = in_mask[(size_t)node*Nn + tid];
        s_idx[1][tid] = out_idx [(size_t)node*Nn + tid];
        s_msk[1][tid] = out_mask[(size_t)node*Nn + tid];
    }
    __syncthreads();

    const float* Hb = H + (size_t)b*Ss*SD;
    for (int d = tid; d < SD; d += blockDim.x) {
        float ai = 0.f, ao = 0.f;
        #pragma unroll
        for (int n = 0; n < Nn; n++) {
            ai += s_msk[0][n] * Hb[(size_t)s_idx[0][n]*SD + d];
            ao += s_msk[1][n] * Hb[(size_t)s_idx[1][n]*SD + d];
        }
        __nv_bfloat16 hi, lo;
        split2(ai * sm, hi, lo);
        g_hin_hi[(size_t)node*KP2 + d] = hi;  g_hin_lo[(size_t)node*KP2 + d] = lo;
        split2(ao * sm, hi, lo);
        g_hout_hi[(size_t)node*KP2 + d] = hi; g_hout_lo[(size_t)node*KP2 + d] = lo;
    }
    for (int j = tid; j < ED; j += blockDim.x) {
        __nv_bfloat16 hi, lo;
        split2(sm * g_iedge[(size_t)node*ED + j], hi, lo);
        g_hin_hi[(size_t)node*KP2 + SD + j] = hi;  g_hin_lo[(size_t)node*KP2 + SD + j] = lo;
        split2(sm * g_oedge[(size_t)node*ED + j], hi, lo);
        g_hout_hi[(size_t)node*KP2 + SD + j] = hi; g_hout_lo[(size_t)node*KP2 + SD + j] = lo;
    }
}

// ---------------- mma.sync split-bf16 GEMM + fused LSTM epilogue ----------------
// SMEM stage: 4 matrices (Ah, Al, Bh, Bl), each 128 rows x 32 halves,
// row pitch 80B (64B data + 16B pad -> ldmatrix conflict-free). Stage=40960B, 2 stages.
#define ROWP 80
#define MATB 10240
#define STAGEB 40960
#define SMEM_TOT (2*STAGEB)

template<int KPAD>
__device__ __forceinline__ void load_chunk(uint32_t st,
    const __nv_bfloat16* __restrict__ Ah, const __nv_bfloat16* __restrict__ Al,
    const __nv_bfloat16* __restrict__ Bh, const __nv_bfloat16* __restrict__ Bl,
    int tid)
{
    #pragma unroll
    for (int i = 0; i < 8; i++) {
        const __nv_bfloat16* base = (i < 2) ? Ah : (i < 4) ? Al : (i < 6) ? Bh : Bl;
        int mat = i >> 1;
        int row = ((i & 1) << 6) + (tid >> 2);
        int seg = tid & 3;
        const char* src = (const char*)(base + (size_t)row * KPAD) + seg * 16;
        uint32_t dst = st + mat * MATB + row * ROWP + seg * 16;
        cpasync16(dst, src);
    }
}

// MODE 0: Cout[row][NT] = D + bias_i
// MODE 1: gates = D + w_terms -> LSTM -> Cout = h (SD layout), cell updated
// MODE 2: MODE 1 + finalH/finalC
template<int KPAD, int MODE>
__global__ __launch_bounds__(256, 1)
void mma_gemm(const __nv_bfloat16* __restrict__ Ahi0, const __nv_bfloat16* __restrict__ Alo0,
              const __nv_bfloat16* __restrict__ Ahi1, const __nv_bfloat16* __restrict__ Alo1,
              const __nv_bfloat16* __restrict__ Bhi0, const __nv_bfloat16* __restrict__ Blo0,
              const __nv_bfloat16* __restrict__ Bhi1, const __nv_bfloat16* __restrict__ Blo1,
              const float* __restrict__ wob,
              const float* __restrict__ seq_mask,
              float* __restrict__ Cout,
              float* __restrict__ cell,
              float* __restrict__ finalH, float* __restrict__ finalC,
              int first)
{
    extern __shared__ char smem[];
    uint32_t sb = smem_u32(smem);
    int tid = threadIdx.x;
    int wid = tid >> 5, lane = tid & 31;
    int wm = wid >> 2, wn = wid & 3;       // warp 2x4: 64 rows x 32 cols
    int row0 = blockIdx.x * 128;
    int n0   = blockIdx.y * 128;

    const int KC = KPAD / 32;
    const int NC = 2 * KC;

    float acc[4][4][4];
    #pragma unroll
    for (int a = 0; a < 4; a++)
        #pragma unroll
        for (int b = 0; b < 4; b++)
            #pragma unroll
            for (int c = 0; c < 4; c++) acc[a][b][c] = 0.f;

    // chunk pointer helper (dir concat: chunks [0,KC) dir0, [KC,2KC) dir1)
    auto Aptr = [&](int ci, int which) -> const __nv_bfloat16* {  // which: 0=hi 1=lo
        int dir = ci >= KC;
        int k0 = (ci - (dir ? KC : 0)) * 32;
        const __nv_bfloat16* p = dir ? (which ? Alo1 : Ahi1) : (which ? Alo0 : Ahi0);
        return p + (size_t)row0 * KPAD + k0;
    };
    auto Bptr = [&](int ci, int which) -> const __nv_bfloat16* {
        int dir = ci >= KC;
        int k0 = (ci - (dir ? KC : 0)) * 32;
        const __nv_bfloat16* p = dir ? (which ? Blo1 : Bhi1) : (which ? Blo0 : Bhi0);
        return p + (size_t)n0 * KPAD + k0;
    };

    // ldmatrix lane-address components
    uint32_t aAddr = (uint32_t)((wm * 64 + (lane & 15)) * ROWP + ((lane >> 4) << 4));
    uint32_t bRow  = (uint32_t)(wn * 32 + (lane & 7) + ((lane >> 4) << 3));
    uint32_t bAddr = bRow * ROWP + (((lane >> 3) & 1) << 4);

    // prologue: chunk 0
    load_chunk<KPAD>(sb, Aptr(0,0), Aptr(0,1), Bptr(0,0), Bptr(0,1), tid);
    CP_COMMIT();

    for (int ci = 0; ci < NC; ci++) {
        if (ci + 1 < NC) {
            uint32_t st = sb + (uint32_t)((ci + 1) & 1) * STAGEB;
            load_chunk<KPAD>(st, Aptr(ci+1,0), Aptr(ci+1,1), Bptr(ci+1,0), Bptr(ci+1,1), tid);
        }
        CP_COMMIT();
        CP_WAIT(1);
        __syncthreads();

        uint32_t st = sb + (uint32_t)(ci & 1) * STAGEB;
        #pragma unroll
        for (int k16 = 0; k16 < 2; k16++) {
            uint32_t ko = (uint32_t)(k16 * 32);
            uint32_t aH[4][4], aL[4][4], bH[2][4], bL[2][4];
            #pragma unroll
            for (int tm = 0; tm < 4; tm++) {
                ldm_x4(aH[tm], st + 0*MATB + aAddr + (uint32_t)(tm*16*ROWP) + ko);
                ldm_x4(aL[tm], st + 1*MATB + aAddr + (uint32_t)(tm*16*ROWP) + ko);
            }
            #pragma unroll
            for (int p = 0; p < 2; p++) {
                ldm_x4(bH[p], st + 2*MATB + bAddr + (uint32_t)(p*16*ROWP) + ko);
                ldm_x4(bL[p], st + 3*MATB + bAddr + (uint32_t)(p*16*ROWP) + ko);
            }
            #pragma unroll
            for (int tm = 0; tm < 4; tm++) {
                #pragma unroll
                for (int tn = 0; tn < 4; tn++) {
                    int p = tn >> 1, h = (tn & 1) * 2;
                    mma16816(acc[tm][tn], aH[tm], bH[p][h], bH[p][h+1]);
                    mma16816(acc[tm][tn], aH[tm], bL[p][h], bL[p][h+1]);
                    mma16816(acc[tm][tn], aL[tm], bH[p][h], bH[p][h+1]);
                }
            }
        }
        __syncthreads();
    }

    // ---------------- stage accumulators to smem (128 x 136 floats) ----------------
    float* sC = (float*)smem;
    #pragma unroll
    for (int tm = 0; tm < 4; tm++) {
        #pragma unroll
        for (int tn = 0; tn < 4; tn++) {
            #pragma unroll
            for (int r = 0; r < 4; r++) {
                int row = wm*64 + tm*16 + (lane >> 2) + ((r >> 1) << 3);
                int nn  = wn*32 + tn*8 + (lane & 3)*2 + (r & 1);
                sC[row * 136 + nn] = acc[tm][tn][r];
            }
        }
    }
    __syncthreads();

    // ---------------- epilogue ----------------
    if (MODE == 0) {
        #pragma unroll
        for (int j = 0; j < 16; j++) {
            int item = j * 256 + tid;
            int row = item >> 5, q = item & 31;
            float4 v  = *reinterpret_cast<float4*>(sC + row * 136 + q * 4);
            float4 bv = *reinterpret_cast<const float4*>(wob + n0 + q * 4);
            v.x += bv.x; v.y += bv.y; v.z += bv.z; v.w += bv.w;
            *reinterpret_cast<float4*>(Cout + (size_t)(row0 + row) * NT + n0 + q * 4) = v;
        }
    } else {
        int c0g = n0 >> 2;
        #pragma unroll
        for (int j = 0; j < 16; j++) {
            int item = j * 256 + tid;
            int row = item >> 5, c = item & 31;
            int grow = row0 + row;
            int cg = c0g + c;
            float4 g  = *reinterpret_cast<float4*>(sC + row * 136 + c * 4);
            float4 wv = *reinterpret_cast<const float4*>(wob + (size_t)grow * NT + n0 + c * 4);
            float gi = g.x + wv.x, gf = g.y + wv.y, go = g.z + wv.z, gc = g.w + wv.w;
            float ig = sigf(gi), fg = sigf(gf), og = sigf(go), ci = tanhf(gc);
            float sm = seq_mask[grow];
            float cp = first ? 0.f : cell[(size_t)grow * SD + cg];
            float tc = fg * cp + ig * ci;
            float th = og * tanhf(tc);
            float cv = tc * sm, hv = th * sm;
            cell[(size_t)grow * SD + cg] = cv;
            Cout[(size_t)grow * SD + cg] = hv;
            if (MODE == 2) {
                finalH[(size_t)grow * SD + cg] = hv;
                finalC[(size_t)grow * SD + cg] = cv;
            }
        }
    }
}

// ---------------- launch ----------------
extern "C" void kernel_launch(void* const* d_in, const int* in_sizes, int n_in,
                              void* d_out, int out_size)
{
    const float* word     = (const float*)d_in[0];
    const float* sent     = (const float*)d_in[1];
    const float* seq_mask = (const float*)d_in[2];
    const float* in_mask  = (const float*)d_in[3];
    const float* out_mask = (const float*)d_in[4];
    const float* edge_emb = (const float*)d_in[5];
    const float* Wg_in    = (const float*)d_in[6];
    const float* Ug_in    = (const float*)d_in[7];
    const float* Wg_out   = (const float*)d_in[8];
    const float* Ug_out   = (const float*)d_in[9];
    const float* bvec     = (const float*)d_in[10];
    const int*   in_idx   = (const int*)d_in[11];
    const int*   in_edges = (const int*)d_in[12];
    const int*   out_idx  = (const int*)d_in[13];
    const int*   out_edges= (const int*)d_in[14];
    float* out = (float*)d_out;

    cudaFuncSetAttribute(mma_gemm<KP1,0>, cudaFuncAttributeMaxDynamicSharedMemorySize, SMEM_TOT);
    cudaFuncSetAttribute(mma_gemm<KP2,1>, cudaFuncAttributeMaxDynamicSharedMemorySize, SMEM_TOT);
    cudaFuncSetAttribute(mma_gemm<KP2,2>, cudaFuncAttributeMaxDynamicSharedMemorySize, SMEM_TOT);

    __nv_bfloat16 *p_ireph,*p_irepl,*p_oreph,*p_orepl;
    __nv_bfloat16 *p_hinh,*p_hinl,*p_houth,*p_houtl;
    __nv_bfloat16 *p_Winh,*p_Winl,*p_Wouth,*p_Woutl,*p_Uinh,*p_Uinl,*p_Uouth,*p_Uoutl;
    float *p_bias,*p_wt,*p_cell;
    cudaGetSymbolAddress((void**)&p_ireph, g_irep_hi);
    cudaGetSymbolAddress((void**)&p_irepl, g_irep_lo);
    cudaGetSymbolAddress((void**)&p_oreph, g_orep_hi);
    cudaGetSymbolAddress((void**)&p_orepl, g_orep_lo);
    cudaGetSymbolAddress((void**)&p_hinh,  g_hin_hi);
    cudaGetSymbolAddress((void**)&p_hinl,  g_hin_lo);
    cudaGetSymbolAddress((void**)&p_houth, g_hout_hi);
    cudaGetSymbolAddress((void**)&p_houtl, g_hout_lo);
    cudaGetSymbolAddress((void**)&p_Winh,  g_Win_hi);
    cudaGetSymbolAddress((void**)&p_Winl,  g_Win_lo);
    cudaGetSymbolAddress((void**)&p_Wouth, g_Wout_hi);
    cudaGetSymbolAddress((void**)&p_Woutl, g_Wout_lo);
    cudaGetSymbolAddress((void**)&p_Uinh,  g_Uin_hi);
    cudaGetSymbolAddress((void**)&p_Uinl,  g_Uin_lo);
    cudaGetSymbolAddress((void**)&p_Uouth, g_Uout_hi);
    cudaGetSymbolAddress((void**)&p_Uoutl, g_Uout_lo);
    cudaGetSymbolAddress((void**)&p_bias,  g_bias_i);
    cudaGetSymbolAddress((void**)&p_wt,    g_wterms);
    cudaGetSymbolAddress((void**)&p_cell,  g_cell);

    const size_t GS = (size_t)Mrows * SD;
    dim3 tb(32, 8);

    // 1) weight transpose + split
    conv_w_kernel<NK1,KP1><<<dim3(KP1/32, SD/32, 4), tb>>>(Wg_in,  p_Winh,  p_Winl);
    conv_w_kernel<NK1,KP1><<<dim3(KP1/32, SD/32, 4), tb>>>(Wg_out, p_Wouth, p_Woutl);
    conv_w_kernel<NK2,KP2><<<dim3(KP2/32, SD/32, 4), tb>>>(Ug_in,  p_Uinh,  p_Uinl);
    conv_w_kernel<NK2,KP2><<<dim3(KP2/32, SD/32, 4), tb>>>(Ug_out, p_Uouth, p_Uoutl);
    bias_kernel<<<NT/256, 256>>>(bvec);

    // 2) static neighbor sums
    prep_rep_kernel<<<Mrows, 128>>>(word, edge_emb, in_idx, in_edges, in_mask,
                                    out_idx, out_edges, out_mask);

    // 3) w_terms GEMM
    {
        dim3 grid(Mrows/128, NT/128);
        mma_gemm<KP1,0><<<grid, 256, SMEM_TOT>>>(
            p_ireph, p_irepl, p_oreph, p_orepl,
            p_Winh, p_Winl, p_Wouth, p_Woutl,
            p_bias, seq_mask, p_wt, nullptr, nullptr, nullptr, 0);
    }

    // 4) layers
    for (int l = 0; l < NLAYERS; l++) {
        const float* H = (l == 0) ? sent : (out + (size_t)(l-1)*GS);
        gather_h_kernel<<<Mrows, 256>>>(H, seq_mask, in_idx, in_mask, out_idx, out_mask);

        dim3 grid(Mrows/128, NT/128);
        float* repL = out + (size_t)l*GS;
        if (l < NLAYERS-1) {
            mma_gemm<KP2,1><<<grid, 256, SMEM_TOT>>>(
                p_hinh, p_hinl, p_houth, p_houtl,
                p_Uinh, p_Uinl, p_Uouth, p_Uoutl,
                p_wt, seq_mask, repL, p_cell, nullptr, nullptr, (l == 0) ? 1 : 0);
        } else {
            mma_gemm<KP2,2><<<grid, 256, SMEM_TOT>>>(
                p_hinh, p_hinl, p_houth, p_houtl,
                p_Uinh, p_Uinl, p_Uouth, p_Uoutl,
                p_wt, seq_mask, repL, p_cell, out + 3*GS, out + 4*GS, 0);
        }
    }
}

// round 6
// speedup vs baseline: 4.6210x; 1.5633x over previous
#include <cuda_runtime.h>
#include <cuda_fp16.h>
#include <math.h>
#include <stdint.h>

// ---------------- static problem shape ----------------
#define Bb 16
#define Ss 512
#define Nn 16
#define WD 300
#define ED 64
#define SD 512
#define NK1 364           // WD+ED
#define KP1 384           // padded to 32
#define KP2 576           // SD+ED (Ug row count)
#define Mrows (Bb*Ss)     // 8192
#define NT 2048           // 4 gates * SD, interleaved n = c*4+g
#define NLAYERS 3

// ---------------- scratch (device globals; no allocations) ----------------
__device__ __align__(256) __half g_irep  [(size_t)Mrows*KP1];   // word+edge (no sm)
__device__ __align__(256) __half g_orep  [(size_t)Mrows*KP1];
__device__ __align__(256) __half g_iedgeS[(size_t)Mrows*ED];    // sm * edge_sum
__device__ __align__(256) __half g_oedgeS[(size_t)Mrows*ED];
__device__ __align__(256) __half g_hin   [(size_t)Mrows*SD];
__device__ __align__(256) __half g_hout  [(size_t)Mrows*SD];
__device__ __align__(256) __half g_Win_hi [(size_t)NT*KP1];
__device__ __align__(256) __half g_Win_lo [(size_t)NT*KP1];
__device__ __align__(256) __half g_Wout_hi[(size_t)NT*KP1];
__device__ __align__(256) __half g_Wout_lo[(size_t)NT*KP1];
__device__ __align__(256) __half g_Uin_hi [(size_t)NT*KP2];
__device__ __align__(256) __half g_Uin_lo [(size_t)NT*KP2];
__device__ __align__(256) __half g_Uout_hi[(size_t)NT*KP2];
__device__ __align__(256) __half g_Uout_lo[(size_t)NT*KP2];
__device__ __align__(256) float  g_bias_i[NT];
__device__ __align__(256) float  g_wterms[(size_t)Mrows*NT];
__device__ __align__(256) float  g_cell  [(size_t)Mrows*SD];

// ---------------- helpers ----------------
__device__ __forceinline__ uint32_t smem_u32(const void* p) {
    uint32_t a;
    asm("{ .reg .u64 t; cvta.to.shared.u64 t, %1; cvt.u32.u64 %0, t; }" : "=r"(a) : "l"(p));
    return a;
}
__device__ __forceinline__ void cpasync16(uint32_t dst, const void* src) {
    asm volatile("cp.async.ca.shared.global [%0], [%1], 16;" :: "r"(dst), "l"(src));
}
#define CP_COMMIT() asm volatile("cp.async.commit_group;" ::: "memory")
#define CP_WAIT(n)  asm volatile("cp.async.wait_group %0;" :: "n"(n) : "memory")

__device__ __forceinline__ void ldm_x4(uint32_t* r, uint32_t addr) {
    asm volatile("ldmatrix.sync.aligned.m8n8.x4.shared.b16 {%0,%1,%2,%3}, [%4];"
        : "=r"(r[0]), "=r"(r[1]), "=r"(r[2]), "=r"(r[3]) : "r"(addr));
}
__device__ __forceinline__ void mma16816(float* d, const uint32_t* a, uint32_t b0, uint32_t b1) {
    asm volatile("mma.sync.aligned.m16n8k16.row.col.f32.f16.f16.f32 "
        "{%0,%1,%2,%3}, {%4,%5,%6,%7}, {%8,%9}, {%0,%1,%2,%3};"
        : "+f"(d[0]), "+f"(d[1]), "+f"(d[2]), "+f"(d[3])
        : "r"(a[0]), "r"(a[1]), "r"(a[2]), "r"(a[3]), "r"(b0), "r"(b1));
}
__device__ __forceinline__ void split2h(float v, __half& hi, __half& lo) {
    hi = __float2half_rn(v);
    lo = __float2half_rn(v - __half2float(hi));
}
__device__ __forceinline__ float sigf(float x) { return 1.f / (1.f + __expf(-x)); }

// ---------------- weight transpose + split: W[g][k][c] -> Bt[(c*4+g)][k] fp16 hi/lo ----------------
template<int KSRC, int KPAD>
__global__ void conv_w_kernel(const float* __restrict__ W,
                              __half* __restrict__ dhi,
                              __half* __restrict__ dlo)
{
    __shared__ float t[32][33];
    int g = blockIdx.z, k0 = blockIdx.x * 32, c0 = blockIdx.y * 32;
    int tx = threadIdx.x, ty = threadIdx.y;   // 32 x 8
    #pragma unroll
    for (int i = 0; i < 4; i++) {
        int k = k0 + ty + i * 8;
        float v = (k < KSRC) ? W[((size_t)g * KSRC + k) * SD + c0 + tx] : 0.f;
        t[ty + i * 8][tx] = v;
    }
    __syncthreads();
    #pragma unroll
    for (int i = 0; i < 4; i++) {
        int c = ty + i * 8;
        int n = (c0 + c) * 4 + g;
        float v = t[tx][c];
        __half hi, lo; split2h(v, hi, lo);
        dhi[(size_t)n * KPAD + k0 + tx] = hi;
        dlo[(size_t)n * KPAD + k0 + tx] = lo;
    }
}

__global__ void bias_kernel(const float* __restrict__ b) {
    int n = blockIdx.x * 256 + threadIdx.x;
    if (n < NT) g_bias_i[n] = b[(n & 3) * SD + (n >> 2)];
}

// ---------------- static neighbor word+edge sums ----------------
__global__ void prep_rep_kernel(const float* __restrict__ word,
                                const float* __restrict__ edge_emb,
                                const float* __restrict__ seq_mask,
                                const int* __restrict__ in_idx,
                                const int* __restrict__ in_edges,
                                const float* __restrict__ in_mask,
                                const int* __restrict__ out_idx,
                                const int* __restrict__ out_edges,
                                const float* __restrict__ out_mask)
{
    int node = blockIdx.x;
    int b = node / Ss;
    float sm = seq_mask[node];
    __shared__ int   s_idx [2][Nn];
    __shared__ int   s_edge[2][Nn];
    __shared__ float s_msk [2][Nn];
    int tid = threadIdx.x;
    if (tid < Nn) {
        s_idx [0][tid] = in_idx  [(size_t)node*Nn + tid];
        s_edge[0][tid] = in_edges[(size_t)node*Nn + tid];
        s_msk [0][tid] = in_mask [(size_t)node*Nn + tid];
        s_idx [1][tid] = out_idx  [(size_t)node*Nn + tid];
        s_edge[1][tid] = out_edges[(size_t)node*Nn + tid];
        s_msk [1][tid] = out_mask [(size_t)node*Nn + tid];
    }
    __syncthreads();

    #pragma unroll
    for (int dir = 0; dir < 2; dir++) {
        __half* rep = dir ? g_orep : g_irep;
        __half* edS = dir ? g_oedgeS : g_iedgeS;
        for (int d = tid; d < WD; d += blockDim.x) {
            float acc = 0.f;
            #pragma unroll
            for (int n = 0; n < Nn; n++)
                acc += s_msk[dir][n] * word[((size_t)b*Ss + s_idx[dir][n])*WD + d];
            rep[(size_t)node*KP1 + d] = __float2half_rn(acc);
        }
        for (int d = tid; d < ED; d += blockDim.x) {
            float acc = 0.f;
            #pragma unroll
            for (int n = 0; n < Nn; n++)
                acc += s_msk[dir][n] * edge_emb[(size_t)s_edge[dir][n]*ED + d];
            rep[(size_t)node*KP1 + WD + d] = __float2half_rn(acc);
            edS[(size_t)node*ED + d] = __float2half_rn(acc * sm);
        }
        for (int d = NK1 + tid; d < KP1; d += blockDim.x)
            rep[(size_t)node*KP1 + d] = __float2half_rn(0.f);
    }
}

// ---------------- per-layer hidden gather (float4, single fp16 out) ----------------
__global__ void gather_h_kernel(const float* __restrict__ H,
                                const float* __restrict__ seq_mask,
                                const int* __restrict__ in_idx,
                                const float* __restrict__ in_mask,
                                const int* __restrict__ out_idx,
                                const float* __restrict__ out_mask)
{
    int node = blockIdx.x;
    int b = node / Ss;
    float sm = seq_mask[node];
    __shared__ int   s_idx[2][Nn];
    __shared__ float s_msk[2][Nn];
    int tid = threadIdx.x;   // 128 threads, each owns 4 dims
    if (tid < Nn) {
        s_idx[0][tid] = in_idx [(size_t)node*Nn + tid];
        s_msk[0][tid] = in_mask[(size_t)node*Nn + tid];
        s_idx[1][tid] = out_idx [(size_t)node*Nn + tid];
        s_msk[1][tid] = out_mask[(size_t)node*Nn + tid];
    }
    __syncthreads();

    const float4* Hb4 = reinterpret_cast<const float4*>(H + (size_t)b*Ss*SD);
    float4 ai = make_float4(0,0,0,0), ao = make_float4(0,0,0,0);
    #pragma unroll
    for (int n = 0; n < Nn; n++) {
        float m0 = s_msk[0][n];
        float4 v = Hb4[(size_t)s_idx[0][n]*(SD/4) + tid];
        ai.x += m0*v.x; ai.y += m0*v.y; ai.z += m0*v.z; ai.w += m0*v.w;
        float m1 = s_msk[1][n];
        float4 w = Hb4[(size_t)s_idx[1][n]*(SD/4) + tid];
        ao.x += m1*w.x; ao.y += m1*w.y; ao.z += m1*w.z; ao.w += m1*w.w;
    }
    __half2* pin  = reinterpret_cast<__half2*>(g_hin  + (size_t)node*SD) + tid*2;
    __half2* pout = reinterpret_cast<__half2*>(g_hout + (size_t)node*SD) + tid*2;
    pin[0]  = __floats2half2_rn(ai.x*sm, ai.y*sm);
    pin[1]  = __floats2half2_rn(ai.z*sm, ai.w*sm);
    pout[0] = __floats2half2_rn(ao.x*sm, ao.y*sm);
    pout[1] = __floats2half2_rn(ao.z*sm, ao.w*sm);
}

// ---------------- segmented fp16 2-product GEMM + fused LSTM epilogue ----------------
// For each K segment: C += A_seg * (Bh_seg + Bl_seg)^T
#define ROWP 80
#define MATB 10240          // 128 rows * 80B
#define STAGEB (3*MATB)     // A, Bh, Bl
#define NSTAGE 3
#define SMEM_TOT (NSTAGE*STAGEB)

struct Seg { const __half* A; const __half* Bh; const __half* Bl; int apitch, bpitch, nchunk; };
struct SegList { Seg s[4]; int nseg; };

__device__ __forceinline__ void chunk_src(const SegList& L, int idx, int row0, int n0,
    const __half*& A, const __half*& Bh, const __half*& Bl, int& ap, int& bp)
{
    #pragma unroll
    for (int s = 0; s < 4; s++) {
        if (s < L.nseg) {
            int n = L.s[s].nchunk;
            if (idx < n) {
                int k0 = idx * 32;
                ap = L.s[s].apitch; bp = L.s[s].bpitch;
                A  = L.s[s].A  + (size_t)row0 * ap + k0;
                Bh = L.s[s].Bh + (size_t)n0  * bp + k0;
                Bl = L.s[s].Bl + (size_t)n0  * bp + k0;
                return;
            }
            idx -= n;
        }
    }
}

__device__ __forceinline__ void load_chunk(uint32_t st,
    const __half* __restrict__ A, int ap,
    const __half* __restrict__ Bh, const __half* __restrict__ Bl, int bp, int tid)
{
    #pragma unroll
    for (int i = 0; i < 2; i++) {
        int idx = tid + i * 256;
        int row = idx >> 2, seg = idx & 3;
        uint32_t doff = (uint32_t)(row * ROWP + seg * 16);
        cpasync16(st + 0*MATB + doff, (const char*)(A  + (size_t)row * ap) + seg * 16);
        cpasync16(st + 1*MATB + doff, (const char*)(Bh + (size_t)row * bp) + seg * 16);
        cpasync16(st + 2*MATB + doff, (const char*)(Bl + (size_t)row * bp) + seg * 16);
    }
}

// MODE 0: Cout[row][NT] = D + bias_i
// MODE 1: gates = D + w_terms -> LSTM -> Cout = h (SD layout), cell updated
// MODE 2: MODE 1 + finalH/finalC
template<int MODE>
__global__ __launch_bounds__(256, 1)
void mma_gemm(SegList L, int NC,
              const float* __restrict__ wob,
              const float* __restrict__ seq_mask,
              float* __restrict__ Cout,
              float* __restrict__ cell,
              float* __restrict__ finalH, float* __restrict__ finalC,
              int first)
{
    extern __shared__ char smem[];
    uint32_t sb = smem_u32(smem);
    int tid = threadIdx.x;
    int wid = tid >> 5, lane = tid & 31;
    int wm = wid >> 2, wn = wid & 3;       // warp 2x4: 64 rows x 32 cols
    int row0 = blockIdx.x * 128;
    int n0   = blockIdx.y * 128;

    float acc[4][4][4];
    #pragma unroll
    for (int a = 0; a < 4; a++)
        #pragma unroll
        for (int b = 0; b < 4; b++)
            #pragma unroll
            for (int c = 0; c < 4; c++) acc[a][b][c] = 0.f;

    uint32_t aAddr = (uint32_t)((wm * 64 + (lane & 15)) * ROWP + ((lane >> 4) << 4));
    uint32_t bRow  = (uint32_t)(wn * 32 + (lane & 7) + ((lane >> 4) << 3));
    uint32_t bAddr = bRow * ROWP + (((lane >> 3) & 1) << 4);

    // prologue: 2 chunks
    {
        const __half *A, *Bh, *Bl; int ap, bp;
        chunk_src(L, 0, row0, n0, A, Bh, Bl, ap, bp);
        load_chunk(sb, A, ap, Bh, Bl, bp, tid);
        CP_COMMIT();
        if (NC > 1) {
            chunk_src(L, 1, row0, n0, A, Bh, Bl, ap, bp);
            load_chunk(sb + STAGEB, A, ap, Bh, Bl, bp, tid);
        }
        CP_COMMIT();
    }

    int stage = 0;
    for (int ci = 0; ci < NC; ci++) {
        if (ci + 2 < NC) {
            int ls = stage + 2; if (ls >= NSTAGE) ls -= NSTAGE;
            const __half *A, *Bh, *Bl; int ap, bp;
            chunk_src(L, ci + 2, row0, n0, A, Bh, Bl, ap, bp);
            load_chunk(sb + (uint32_t)ls * STAGEB, A, ap, Bh, Bl, bp, tid);
        }
        CP_COMMIT();
        CP_WAIT(2);
        __syncthreads();

        uint32_t st = sb + (uint32_t)stage * STAGEB;
        #pragma unroll
        for (int k16 = 0; k16 < 2; k16++) {
            uint32_t ko = (uint32_t)(k16 * 32);
            uint32_t aH[4][4], bH[2][4], bL[2][4];
            #pragma unroll
            for (int tm = 0; tm < 4; tm++)
                ldm_x4(aH[tm], st + 0*MATB + aAddr + (uint32_t)(tm*16*ROWP) + ko);
            #pragma unroll
            for (int p = 0; p < 2; p++) {
                ldm_x4(bH[p], st + 1*MATB + bAddr + (uint32_t)(p*16*ROWP) + ko);
                ldm_x4(bL[p], st + 2*MATB + bAddr + (uint32_t)(p*16*ROWP) + ko);
            }
            #pragma unroll
            for (int tm = 0; tm < 4; tm++) {
                #pragma unroll
                for (int tn = 0; tn < 4; tn++) {
                    int p = tn >> 1, h = (tn & 1) * 2;
                    mma16816(acc[tm][tn], aH[tm], bH[p][h], bH[p][h+1]);
                    mma16816(acc[tm][tn], aH[tm], bL[p][h], bL[p][h+1]);
                }
            }
        }
        __syncthreads();
        stage++; if (stage >= NSTAGE) stage = 0;
    }

    // ---------------- stage accumulators to smem (128 x 136 floats) ----------------
    float* sC = (float*)smem;
    #pragma unroll
    for (int tm = 0; tm < 4; tm++) {
        #pragma unroll
        for (int tn = 0; tn < 4; tn++) {
            #pragma unroll
            for (int r = 0; r < 4; r++) {
                int row = wm*64 + tm*16 + (lane >> 2) + ((r >> 1) << 3);
                int nn  = wn*32 + tn*8 + (lane & 3)*2 + (r & 1);
                sC[row * 136 + nn] = acc[tm][tn][r];
            }
        }
    }
    __syncthreads();

    // ---------------- epilogue ----------------
    if (MODE == 0) {
        #pragma unroll
        for (int j = 0; j < 16; j++) {
            int item = j * 256 + tid;
            int row = item >> 5, q = item & 31;
            float4 v  = *reinterpret_cast<float4*>(sC + row * 136 + q * 4);
            float4 bv = *reinterpret_cast<const float4*>(wob + n0 + q * 4);
            v.x += bv.x; v.y += bv.y; v.z += bv.z; v.w += bv.w;
            *reinterpret_cast<float4*>(Cout + (size_t)(row0 + row) * NT + n0 + q * 4) = v;
        }
    } else {
        int c0g = n0 >> 2;
        #pragma unroll
        for (int j = 0; j < 16; j++) {
            int item = j * 256 + tid;
            int row = item >> 5, c = item & 31;
            int grow = row0 + row;
            int cg = c0g + c;
            float4 g  = *reinterpret_cast<float4*>(sC + row * 136 + c * 4);
            float4 wv = *reinterpret_cast<const float4*>(wob + (size_t)grow * NT + n0 + c * 4);
            float gi = g.x + wv.x, gf = g.y + wv.y, go = g.z + wv.z, gc = g.w + wv.w;
            float ig = sigf(gi), fg = sigf(gf), og = sigf(go), ci = tanhf(gc);
            float sm = seq_mask[grow];
            float cp = first ? 0.f : cell[(size_t)grow * SD + cg];
            float tc = fg * cp + ig * ci;
            float th = og * tanhf(tc);
            float cv = tc * sm, hv = th * sm;
            cell[(size_t)grow * SD + cg] = cv;
            Cout[(size_t)grow * SD + cg] = hv;
            if (MODE == 2) {
                finalH[(size_t)grow * SD + cg] = hv;
                finalC[(size_t)grow * SD + cg] = cv;
            }
        }
    }
}

// ---------------- launch ----------------
extern "C" void kernel_launch(void* const* d_in, const int* in_sizes, int n_in,
                              void* d_out, int out_size)
{
    const float* word     = (const float*)d_in[0];
    const float* sent     = (const float*)d_in[1];
    const float* seq_mask = (const float*)d_in[2];
    const float* in_mask  = (const float*)d_in[3];
    const float* out_mask = (const float*)d_in[4];
    const float* edge_emb = (const float*)d_in[5];
    const float* Wg_in    = (const float*)d_in[6];
    const float* Ug_in    = (const float*)d_in[7];
    const float* Wg_out   = (const float*)d_in[8];
    const float* Ug_out   = (const float*)d_in[9];
    const float* bvec     = (const float*)d_in[10];
    const int*   in_idx   = (const int*)d_in[11];
    const int*   in_edges = (const int*)d_in[12];
    const int*   out_idx  = (const int*)d_in[13];
    const int*   out_edges= (const int*)d_in[14];
    float* out = (float*)d_out;

    cudaFuncSetAttribute(mma_gemm<0>, cudaFuncAttributeMaxDynamicSharedMemorySize, SMEM_TOT);
    cudaFuncSetAttribute(mma_gemm<1>, cudaFuncAttributeMaxDynamicSharedMemorySize, SMEM_TOT);
    cudaFuncSetAttribute(mma_gemm<2>, cudaFuncAttributeMaxDynamicSharedMemorySize, SMEM_TOT);

    __half *p_irep,*p_orep,*p_iedS,*p_oedS,*p_hin,*p_hout;
    __half *p_Winh,*p_Winl,*p_Wouth,*p_Woutl,*p_Uinh,*p_Uinl,*p_Uouth,*p_Uoutl;
    float *p_bias,*p_wt,*p_cell;
    cudaGetSymbolAddress((void**)&p_irep,  g_irep);
    cudaGetSymbolAddress((void**)&p_orep,  g_orep);
    cudaGetSymbolAddress((void**)&p_iedS,  g_iedgeS);
    cudaGetSymbolAddress((void**)&p_oedS,  g_oedgeS);
    cudaGetSymbolAddress((void**)&p_hin,   g_hin);
    cudaGetSymbolAddress((void**)&p_hout,  g_hout);
    cudaGetSymbolAddress((void**)&p_Winh,  g_Win_hi);
    cudaGetSymbolAddress((void**)&p_Winl,  g_Win_lo);
    cudaGetSymbolAddress((void**)&p_Wouth, g_Wout_hi);
    cudaGetSymbolAddress((void**)&p_Woutl, g_Wout_lo);
    cudaGetSymbolAddress((void**)&p_Uinh,  g_Uin_hi);
    cudaGetSymbolAddress((void**)&p_Uinl,  g_Uin_lo);
    cudaGetSymbolAddress((void**)&p_Uouth, g_Uout_hi);
    cudaGetSymbolAddress((void**)&p_Uoutl, g_Uout_lo);
    cudaGetSymbolAddress((void**)&p_bias,  g_bias_i);
    cudaGetSymbolAddress((void**)&p_wt,    g_wterms);
    cudaGetSymbolAddress((void**)&p_cell,  g_cell);

    const size_t GS = (size_t)Mrows * SD;
    dim3 tb(32, 8);

    // 1) weight transpose + split
    conv_w_kernel<NK1,KP1><<<dim3(KP1/32, SD/32, 4), tb>>>(Wg_in,  p_Winh,  p_Winl);
    conv_w_kernel<NK1,KP1><<<dim3(KP1/32, SD/32, 4), tb>>>(Wg_out, p_Wouth, p_Woutl);
    conv_w_kernel<KP2,KP2><<<dim3(KP2/32, SD/32, 4), tb>>>(Ug_in,  p_Uinh,  p_Uinl);
    conv_w_kernel<KP2,KP2><<<dim3(KP2/32, SD/32, 4), tb>>>(Ug_out, p_Uouth, p_Uoutl);
    bias_kernel<<<NT/256, 256>>>(bvec);

    // 2) static neighbor sums
    prep_rep_kernel<<<Mrows, 128>>>(word, edge_emb, seq_mask,
                                    in_idx, in_edges, in_mask,
                                    out_idx, out_edges, out_mask);

    // 3) w_terms GEMM (incl. folded static edge terms of U-GEMMs)
    {
        SegList L;
        L.s[0] = { p_irep, p_Winh,        p_Winl,        KP1, KP1, KP1/32 };
        L.s[1] = { p_orep, p_Wouth,       p_Woutl,       KP1, KP1, KP1/32 };
        L.s[2] = { p_iedS, p_Uinh  + SD,  p_Uinl  + SD,  ED,  KP2, ED/32  };
        L.s[3] = { p_oedS, p_Uouth + SD,  p_Uoutl + SD,  ED,  KP2, ED/32  };
        L.nseg = 4;
        int NC = 2 * (KP1/32) + 2 * (ED/32);   // 28
        dim3 grid(Mrows/128, NT/128);
        mma_gemm<0><<<grid, 256, SMEM_TOT>>>(L, NC, p_bias, seq_mask,
                                             p_wt, nullptr, nullptr, nullptr, 0);
    }

    // 4) layers
    for (int l = 0; l < NLAYERS; l++) {
        const float* H = (l == 0) ? sent : (out + (size_t)(l-1)*GS);
        gather_h_kernel<<<Mrows, 128>>>(H, seq_mask, in_idx, in_mask, out_idx, out_mask);

        SegList L;
        L.s[0] = { p_hin,  p_Uinh,  p_Uinl,  SD, KP2, SD/32 };
        L.s[1] = { p_hout, p_Uouth, p_Uoutl, SD, KP2, SD/32 };
        L.s[2] = L.s[0]; L.s[3] = L.s[0];
        L.nseg = 2;
        int NC = 2 * (SD/32);   // 32
        dim3 grid(Mrows/128, NT/128);
        float* repL = out + (size_t)l*GS;
        if (l < NLAYERS-1) {
            mma_gemm<1><<<grid, 256, SMEM_TOT>>>(L, NC, p_wt, seq_mask,
                                                 repL, p_cell, nullptr, nullptr, (l == 0) ? 1 : 0);
        } else {
            mma_gemm<2><<<grid, 256, SMEM_TOT>>>(L, NC, p_wt, seq_mask,
                                                 repL, p_cell, out + 3*GS, out + 4*GS, 0);
        }
    }
}